// round 1
// baseline (speedup 1.0000x reference)
#include <cuda_runtime.h>
#include <math.h>

// ---------------- static scratch (no allocations allowed) ----------------
#define NMAXV (65*65*65)            // 274625 vertices
#define EMAXV (7*NMAXV)             // 1922375 (anchor,type) edge slots
#define TMAXV (6*64*64*64)          // 1572864 tets
#define SCAN_B 256
#define SCAN_I 8
#define SCAN_CHUNK (SCAN_B*SCAN_I)  // 2048
#define MAXBLK 4096

__device__ float              g_sdf[NMAXV];       // tanh(sdf)
__device__ unsigned char      g_occ[NMAXV];
__device__ float              g_rot[3*NMAXV];     // scale * inv(R) @ [d0,d1,1]
__device__ int                g_edgeScan[EMAXV];  // local-exclusive crossing-flag scan
__device__ int                g_eBlk[MAXBLK];     // per-block sums -> exclusive offsets
__device__ unsigned char      g_tetIdx[TMAXV];
__device__ unsigned long long g_tetScan[TMAXV];   // packed (cnt1 | cnt2<<32) local scan
__device__ unsigned long long g_tBlk[MAXBLK];
__device__ int                g_nv;               // total crossing edges (= output verts)
__device__ int                g_n1;               // total 1-triangle tets

__constant__ int c_path[6][4] = {
    {0,4,6,7},{0,4,5,7},{0,2,6,7},{0,2,3,7},{0,1,5,7},{0,1,3,7}};
__constant__ int c_ntri[16] = {0,1,1,2,1,2,2,1,1,2,2,1,2,1,1,0};
__constant__ int c_tri[16][6] = {
    {-1,-1,-1,-1,-1,-1},
    { 1, 0, 2,-1,-1,-1},
    { 4, 0, 3,-1,-1,-1},
    { 1, 4, 2, 1, 3, 4},
    { 3, 1, 5,-1,-1,-1},
    { 2, 3, 0, 2, 5, 3},
    { 1, 4, 0, 1, 5, 4},
    { 4, 2, 5,-1,-1,-1},
    { 4, 5, 2,-1,-1,-1},
    { 4, 1, 0, 4, 5, 1},
    { 3, 2, 0, 3, 5, 2},
    { 1, 3, 5,-1,-1,-1},
    { 4, 1, 2, 4, 3, 1},
    { 3, 0, 4,-1,-1,-1},
    { 2, 0, 1,-1,-1,-1},
    {-1,-1,-1,-1,-1,-1}};

// ---------------- kernel 1: per-vertex prep ----------------
__global__ void k_prep(const float* __restrict__ sdf_n,
                       const float* __restrict__ dir,
                       const float* __restrict__ rotm,
                       const float* __restrict__ scales,
                       int N, float dscale)
{
    int v = blockIdx.x*blockDim.x + threadIdx.x;
    if (v >= N) return;
    float s = sdf_n[v];
    g_sdf[v] = tanhf(s);
    g_occ[v] = (s > 0.0f) ? 1 : 0;
    float l0 = dscale * tanhf(dir[2*v+0]);
    float l1 = dscale * tanhf(dir[2*v+1]);
    const float* m = rotm + 9*(size_t)v;
    float m00=m[0],m01=m[1],m02=m[2],m10=m[3],m11=m[4],m12=m[5],m20=m[6],m21=m[7],m22=m[8];
    // inverse via adjugate:  inv[j][i] = c_ji / det
    float c00=m11*m22-m12*m21, c01=m02*m21-m01*m22, c02=m01*m12-m02*m11;
    float c10=m12*m20-m10*m22, c11=m00*m22-m02*m20, c12=m02*m10-m00*m12;
    float c20=m10*m21-m11*m20, c21=m01*m20-m00*m21, c22=m00*m11-m01*m10;
    float det = m00*c00 + m01*c10 + m02*c20;
    float f = scales[v] / det;
    g_rot[3*v+0] = (c00*l0 + c01*l1 + c02) * f;
    g_rot[3*v+1] = (c10*l0 + c11*l1 + c12) * f;
    g_rot[3*v+2] = (c20*l0 + c21*l1 + c22) * f;
}

// ---------------- edge enumeration helpers ----------------
__device__ __forceinline__ int edge_flag(int e, int S)
{
    int v = e / 7;
    int t = e - 7*v + 1;                 // 1..7 -> (di,dj,dk)
    int di = (t>>2)&1, dj = (t>>1)&1, dk = t&1;
    int S2 = S*S;
    int i = v / S2; int rem = v - i*S2; int j = rem / S; int k = rem - j*S;
    if (i+di >= S || j+dj >= S || k+dk >= S) return 0;
    int v2 = v + di*S2 + dj*S + dk;
    return (int)(g_occ[v] != g_occ[v2]);
}

// ---------------- kernel 2: edge crossing-flag block scan ----------------
__global__ void k_escan1(int E, int S)
{
    __shared__ int sh[SCAN_B];
    int tid = threadIdx.x;
    int base = blockIdx.x*SCAN_CHUNK + tid*SCAN_I;
    int loc[SCAN_I];
    int sum = 0;
#pragma unroll
    for (int it = 0; it < SCAN_I; ++it) {
        int e = base + it;
        int f = (e < E) ? edge_flag(e, S) : 0;
        loc[it] = sum;
        sum += f;
    }
    sh[tid] = sum; __syncthreads();
    for (int off = 1; off < SCAN_B; off <<= 1) {
        int vv = (tid >= off) ? sh[tid-off] : 0;
        __syncthreads(); sh[tid] += vv; __syncthreads();
    }
    int exc = tid ? sh[tid-1] : 0;
#pragma unroll
    for (int it = 0; it < SCAN_I; ++it) {
        int e = base + it;
        if (e < E) g_edgeScan[e] = exc + loc[it];
    }
    if (tid == SCAN_B-1) g_eBlk[blockIdx.x] = sh[SCAN_B-1];
}

// ---------------- kernel 3: scan of edge block sums ----------------
__global__ void k_emid(int nb)
{
    __shared__ int sh[1024];
    int tid = threadIdx.x;
    int run = 0;
    for (int c0 = 0; c0 < nb; c0 += 1024) {
        int idx = c0 + tid;
        int vv = (idx < nb) ? g_eBlk[idx] : 0;
        sh[tid] = vv; __syncthreads();
        for (int off = 1; off < 1024; off <<= 1) {
            int u = (tid >= off) ? sh[tid-off] : 0;
            __syncthreads(); sh[tid] += u; __syncthreads();
        }
        int exc = run + (tid ? sh[tid-1] : 0);
        if (idx < nb) g_eBlk[idx] = exc;
        run += sh[1023];
        __syncthreads();
    }
    if (tid == 0) g_nv = run;
}

// ---------------- tet helpers ----------------
__device__ __forceinline__ void tet_corners(int r, int R, int S, int cv[4])
{
    int R3 = R*R*R;
    int p = r / R3; int c = r - p*R3;
    int i = c/(R*R); int rem = c - i*R*R; int j = rem/R; int k = rem - j*R;
    int S2 = S*S;
    int v000 = (i*S + j)*S + k;
#pragma unroll
    for (int m = 0; m < 4; ++m) {
        int n = c_path[p][m];
        cv[m] = v000 + ((n>>2)&1)*S2 + ((n>>1)&1)*S + (n&1);
    }
}

// ---------------- kernel 4: tet classify + packed scan ----------------
__global__ void k_tscan1(int T, int R, int S)
{
    __shared__ unsigned long long sh[SCAN_B];
    int tid = threadIdx.x;
    int base = blockIdx.x*SCAN_CHUNK + tid*SCAN_I;
    unsigned long long loc[SCAN_I];
    unsigned long long sum = 0ull;
#pragma unroll
    for (int it = 0; it < SCAN_I; ++it) {
        int r = base + it;
        unsigned long long add = 0ull;
        if (r < T) {
            int cv[4];
            tet_corners(r, R, S, cv);
            int ti = ((int)g_occ[cv[0]]) | ((int)g_occ[cv[1]]<<1)
                   | ((int)g_occ[cv[2]]<<2) | ((int)g_occ[cv[3]]<<3);
            g_tetIdx[r] = (unsigned char)ti;
            int nt = c_ntri[ti];
            add = (unsigned long long)(nt == 1) | ((unsigned long long)(nt == 2) << 32);
        }
        loc[it] = sum;
        sum += add;
    }
    sh[tid] = sum; __syncthreads();
    for (int off = 1; off < SCAN_B; off <<= 1) {
        unsigned long long vv = (tid >= off) ? sh[tid-off] : 0ull;
        __syncthreads(); sh[tid] += vv; __syncthreads();
    }
    unsigned long long exc = tid ? sh[tid-1] : 0ull;
#pragma unroll
    for (int it = 0; it < SCAN_I; ++it) {
        int r = base + it;
        if (r < T) g_tetScan[r] = exc + loc[it];
    }
    if (tid == SCAN_B-1) g_tBlk[blockIdx.x] = sh[SCAN_B-1];
}

// ---------------- kernel 5: scan of tet block sums ----------------
__global__ void k_tmid(int nb)
{
    __shared__ unsigned long long sh[1024];
    int tid = threadIdx.x;
    unsigned long long run = 0ull;
    for (int c0 = 0; c0 < nb; c0 += 1024) {
        int idx = c0 + tid;
        unsigned long long vv = (idx < nb) ? g_tBlk[idx] : 0ull;
        sh[tid] = vv; __syncthreads();
        for (int off = 1; off < 1024; off <<= 1) {
            unsigned long long u = (tid >= off) ? sh[tid-off] : 0ull;
            __syncthreads(); sh[tid] += u; __syncthreads();
        }
        unsigned long long exc = run + (tid ? sh[tid-1] : 0ull);
        if (idx < nb) g_tBlk[idx] = exc;
        run += sh[1023];
        __syncthreads();
    }
    if (tid == 0) g_n1 = (int)(run & 0xffffffffull);
}

// ---------------- kernel 6: emit interpolated vertex features ----------------
__global__ void k_verts(const float* __restrict__ feats, float* __restrict__ out,
                        int E, int S)
{
    int e = blockIdx.x*blockDim.x + threadIdx.x;
    if (e >= E) return;
    int v = e / 7;
    int t = e - 7*v + 1;
    int di = (t>>2)&1, dj = (t>>1)&1, dk = t&1;
    int S2 = S*S;
    int i = v / S2; int rem = v - i*S2; int j = rem / S; int k = rem - j*S;
    if (i+di >= S || j+dj >= S || k+dk >= S) return;
    int v2 = v + di*S2 + dj*S + dk;
    if (g_occ[v] == g_occ[v2]) return;

    int rank = g_edgeScan[e] + g_eBlk[e / SCAN_CHUNK];
    float sa = g_sdf[v], sb = g_sdf[v2];
    float denom = sa - sb;                  // sdf_a + (-sdf_b)
    float wa = -sb / denom;                 // weight on endpoint a (min vid)
    float wb =  sa / denom;                 // weight on endpoint b
    float* o = out + (size_t)rank * 6;
    o[0] = wa*g_rot[3*v+0] + wb*g_rot[3*v2+0];
    o[1] = wa*g_rot[3*v+1] + wb*g_rot[3*v2+1];
    o[2] = wa*g_rot[3*v+2] + wb*g_rot[3*v2+2];
    const float* fa = feats + (size_t)v  * 6 + 3;
    const float* fb = feats + (size_t)v2 * 6 + 3;
    o[3] = wa*fa[0] + wb*fb[0];
    o[4] = wa*fa[1] + wb*fb[1];
    o[5] = wa*fa[2] + wb*fb[2];
}

// ---------------- kernel 7: emit faces ----------------
__global__ void k_faces(float* __restrict__ out, int T, int R, int S)
{
    int r = blockIdx.x*blockDim.x + threadIdx.x;
    if (r >= T) return;
    int ti = g_tetIdx[r];
    int nt = c_ntri[ti];
    if (nt == 0) return;

    int cv[4];
    tet_corners(r, R, S, cv);
    int S2 = S*S;

    const int ea[6] = {0,0,0,1,1,2};
    const int eb[6] = {1,2,3,2,3,3};
    int er[6];
#pragma unroll
    for (int s = 0; s < 6; ++s) {
        int va = cv[ea[s]], vb = cv[eb[s]];
        int d = vb - va;                       // positive, one of 7 offsets
        int di = (d >= S2) ? 1 : 0; int rm = d - di*S2;
        int dj = (rm >= S) ? 1 : 0; int dk = rm - dj*S;
        int t = (di<<2) | (dj<<1) | dk;        // 1..7
        int e = va*7 + t - 1;
        er[s] = g_edgeScan[e] + g_eBlk[e / SCAN_CHUNK];
    }

    unsigned long long sc = g_tetScan[r] + g_tBlk[r / SCAN_CHUNK];
    int s1 = (int)(sc & 0xffffffffull);
    int s2 = (int)(sc >> 32);
    size_t vbase = (size_t)g_nv * 6;
    const int* tt = c_tri[ti];

    if (nt == 1) {
        size_t o = vbase + (size_t)s1 * 3;
        out[o+0] = (float)er[tt[0]];
        out[o+1] = (float)er[tt[1]];
        out[o+2] = (float)er[tt[2]];
    } else {
        size_t o = vbase + ((size_t)g_n1 + 2*(size_t)s2) * 3;
#pragma unroll
        for (int q = 0; q < 6; ++q)
            out[o+q] = (float)er[tt[q]];
    }
}

// ---------------- launch ----------------
extern "C" void kernel_launch(void* const* d_in, const int* in_sizes, int n_in,
                              void* d_out, int out_size)
{
    const float* feats  = (const float*)d_in[0];
    const float* sdf_n  = (const float*)d_in[1];
    const float* dir    = (const float*)d_in[2];
    const float* rotm   = (const float*)d_in[3];
    const float* scales = (const float*)d_in[4];
    // d_in[5] (tet_fx4) and d_in[6] (grid_res) are reconstructed structurally.

    int N = in_sizes[1];
    int S = 1;
    while ((long long)S*S*S < (long long)N) ++S;   // S = R+1 (65 for grid_res 64)
    int R = S - 1;
    int E = 7*N;
    int T = 6*R*R*R;
    float dscale = 4.0f / (float)R;
    float* out = (float*)d_out;

    int nbE = (E + SCAN_CHUNK - 1) / SCAN_CHUNK;
    int nbT = (T + SCAN_CHUNK - 1) / SCAN_CHUNK;

    k_prep  <<<(N + 255)/256, 256>>>(sdf_n, dir, rotm, scales, N, dscale);
    k_escan1<<<nbE, SCAN_B>>>(E, S);
    k_emid  <<<1, 1024>>>(nbE);
    k_tscan1<<<nbT, SCAN_B>>>(T, R, S);
    k_tmid  <<<1, 1024>>>(nbT);
    k_verts <<<(E + 255)/256, 256>>>(feats, out, E, S);
    k_faces <<<(T + 255)/256, 256>>>(out, T, R, S);
}

// round 2
// speedup vs baseline: 1.0206x; 1.0206x over previous
#include <cuda_runtime.h>
#include <math.h>

// ---------------- static scratch ----------------
#define SMAX   65
#define NMAXV  (SMAX*SMAX*SMAX)       // 274625 vertices
#define NWPAD  8832                   // occ bit-words + pad for max offset reads
#define NGMAX  8600                   // 32-anchor edge groups
#define NCMAX  (64*64*64)             // cubes
#define TMAX   (6*NCMAX)              // tets
#define SCAN_B 256
#define SCAN_I 8
#define SCAN_CHUNK 2048
#define MAXBLK 1024

__device__ unsigned           g_occw[NWPAD];      // bit-packed occupancy (pad stays 0)
__device__ float              g_sdf[NMAXV];       // tanh(sdf)
__device__ float              g_rot[3*NMAXV];     // scale * R^T @ [d0,d1,1]
__device__ uint4              g_egrp[NGMAX*2];    // per group: 7 masks + exclusive base
__device__ int                g_eGrpCnt[NGMAX];
__device__ unsigned char      g_cubeCode[NCMAX];  // 8-bit corner occupancy per cube
__device__ unsigned           g_tetScan[TMAX];    // packed (cnt1 lo16 | cnt2 hi16) local scan
__device__ unsigned           g_tBlkP[MAXBLK];    // packed per-block sums
__device__ unsigned long long g_tBlk64[MAXBLK];   // widened exclusive block offsets
__device__ int                g_nv;               // total crossing edges (= output verts)
__device__ int                g_n1;               // total 1-triangle tets

__constant__ int c_path[6][4] = {
    {0,4,6,7},{0,4,5,7},{0,2,6,7},{0,2,3,7},{0,1,5,7},{0,1,3,7}};
__constant__ int c_ntri[16] = {0,1,1,2,1,2,2,1,1,2,2,1,2,1,1,0};
__constant__ int c_tri[16][6] = {
    {-1,-1,-1,-1,-1,-1},
    { 1, 0, 2,-1,-1,-1},
    { 4, 0, 3,-1,-1,-1},
    { 1, 4, 2, 1, 3, 4},
    { 3, 1, 5,-1,-1,-1},
    { 2, 3, 0, 2, 5, 3},
    { 1, 4, 0, 1, 5, 4},
    { 4, 2, 5,-1,-1,-1},
    { 4, 5, 2,-1,-1,-1},
    { 4, 1, 0, 4, 5, 1},
    { 3, 2, 0, 3, 5, 2},
    { 1, 3, 5,-1,-1,-1},
    { 4, 1, 2, 4, 3, 1},
    { 3, 0, 4,-1,-1,-1},
    { 2, 0, 1,-1,-1,-1},
    {-1,-1,-1,-1,-1,-1}};

__device__ __forceinline__ unsigned bits32(int b)
{
    unsigned w0 = g_occw[b >> 5];
    unsigned w1 = g_occw[(b >> 5) + 1];
    return __funnelshift_r(w0, w1, b & 31);
}

// ---------------- kernel 1: per-vertex prep + occ bit-pack ----------------
__global__ void k_prep(const float* __restrict__ sdf_n,
                       const float* __restrict__ dir,
                       const float* __restrict__ rotm,
                       const float* __restrict__ scales,
                       int N, float dscale)
{
    int v = blockIdx.x*blockDim.x + threadIdx.x;
    bool inb = v < N;
    float s = inb ? sdf_n[v] : -1.0f;
    unsigned bal = __ballot_sync(0xffffffffu, s > 0.0f);
    if ((threadIdx.x & 31) == 0) g_occw[v >> 5] = bal;
    if (!inb) return;

    g_sdf[v] = tanhf(s);
    float l0 = dscale * tanhf(dir[2*v+0]);
    float l1 = dscale * tanhf(dir[2*v+1]);
    const float* m = rotm + 9*(size_t)v;
    float sc = scales[v];
    // rotation matrix: inv(R) = R^T
    g_rot[3*v+0] = (m[0]*l0 + m[3]*l1 + m[6]) * sc;
    g_rot[3*v+1] = (m[1]*l0 + m[4]*l1 + m[7]) * sc;
    g_rot[3*v+2] = (m[2]*l0 + m[5]*l1 + m[8]) * sc;
}

// ---------------- kernel 2: edge-group masks + counts, cube codes ----------------
__global__ void k_grp(int N, int S, int NG, int NC, int R)
{
    int t = blockIdx.x*blockDim.x + threadIdx.x;
    int S2 = S*S;

    if (t < NG) {
        int v0 = t << 5;
        int i0 = v0 / S2; int rem = v0 - i0*S2; int j0 = rem / S; int k0 = rem - j0*S;
        int qw = S - k0;                               // wrap position (>=1)
        unsigned pre = (qw >= 32) ? 0xffffffffu : ((1u << (qw & 31)) - 1u);
        int j1 = j0 + 1, i1 = i0; if (j1 == S) { j1 = 0; ++i1; }
        int nvld = N - v0;
        unsigned tailm = (nvld >= 32) ? 0xffffffffu : ((1u << (nvld & 31)) - 1u);
        unsigned A = bits32(v0);
        unsigned mm[7]; int cnt = 0;
#pragma unroll
        for (int tt = 1; tt <= 7; ++tt) {
            int di = (tt>>2)&1, dj = (tt>>1)&1, dk = tt&1;
            int d = di*S2 + dj*S + dk;
            unsigned X = A ^ bits32(v0 + d);
            unsigned vm = (((i0+di < S) && (j0+dj < S)) ? pre : 0u)
                        | (((i1+di < S) && (j1+dj < S)) ? ~pre : 0u);
            if (dk && (qw - 1) < 32) vm &= ~(1u << (qw - 1));   // k == S-1 invalid
            vm &= tailm;
            mm[tt-1] = X & vm;
            cnt += __popc(mm[tt-1]);
        }
        g_egrp[2*t]   = make_uint4(mm[0], mm[1], mm[2], mm[3]);
        g_egrp[2*t+1] = make_uint4(mm[4], mm[5], mm[6], 0u);
        g_eGrpCnt[t]  = cnt;
    }

    if (t < NC) {
        int R2 = R*R;
        int i = t / R2; int rem = t - i*R2; int j = rem / R; int k = rem - j*R;
        int b = (i*S + j)*S + k;
        unsigned p00 = bits32(b)          & 3u;
        unsigned p01 = bits32(b + S)      & 3u;
        unsigned p10 = bits32(b + S2)     & 3u;
        unsigned p11 = bits32(b + S2 + S) & 3u;
        g_cubeCode[t] = (unsigned char)(p00 | (p01 << 2) | (p10 << 4) | (p11 << 6));
    }
}

// ---------------- kernel 3: tet classify + packed scan ----------------
__global__ void k_tscan(int T, int R)
{
    __shared__ unsigned sh[SCAN_B];
    int tid = threadIdx.x;
    int base = blockIdx.x*SCAN_CHUNK + tid*SCAN_I;
    int R3 = R*R*R;
    unsigned loc[SCAN_I], sum = 0u;
#pragma unroll
    for (int it = 0; it < SCAN_I; ++it) {
        int r = base + it;
        unsigned add = 0u;
        if (r < T) {
            int p = r / R3, c = r - p*R3;
            unsigned code = g_cubeCode[c];
            int ti = ((code >> c_path[p][0]) & 1)
                   | (((code >> c_path[p][1]) & 1) << 1)
                   | (((code >> c_path[p][2]) & 1) << 2)
                   | (((code >> c_path[p][3]) & 1) << 3);
            int nt = c_ntri[ti];
            add = (nt == 1) ? 1u : ((nt == 2) ? 0x10000u : 0u);
        }
        loc[it] = sum; sum += add;
    }
    sh[tid] = sum; __syncthreads();
    for (int off = 1; off < SCAN_B; off <<= 1) {
        unsigned v = (tid >= off) ? sh[tid-off] : 0u;
        __syncthreads(); sh[tid] += v; __syncthreads();
    }
    unsigned exc = tid ? sh[tid-1] : 0u;
#pragma unroll
    for (int it = 0; it < SCAN_I; ++it) {
        int r = base + it;
        if (r < T) g_tetScan[r] = exc + loc[it];
    }
    if (tid == SCAN_B-1) g_tBlkP[blockIdx.x] = sh[SCAN_B-1];
}

// ---------------- kernel 4: both mid-level scans (2 blocks) ----------------
__global__ void k_mid(int NG, int nbT)
{
    __shared__ unsigned long long sh[1024];
    int tid = threadIdx.x;
    if (blockIdx.x == 0) {
        int run = 0;
        for (int c0 = 0; c0 < NG; c0 += 1024) {
            int idx = c0 + tid;
            sh[tid] = (idx < NG) ? (unsigned long long)g_eGrpCnt[idx] : 0ull;
            __syncthreads();
            for (int off = 1; off < 1024; off <<= 1) {
                unsigned long long u = (tid >= off) ? sh[tid-off] : 0ull;
                __syncthreads(); sh[tid] += u; __syncthreads();
            }
            int exc = run + (int)(tid ? sh[tid-1] : 0ull);
            if (idx < NG) ((unsigned*)g_egrp)[idx*8 + 7] = (unsigned)exc;
            run += (int)sh[1023];
            __syncthreads();
        }
        if (tid == 0) g_nv = run;
    } else {
        unsigned long long run = 0ull;
        for (int c0 = 0; c0 < nbT; c0 += 1024) {
            int idx = c0 + tid;
            unsigned long long val = 0ull;
            if (idx < nbT) {
                unsigned pkt = g_tBlkP[idx];
                val = (unsigned long long)(pkt & 0xffffu)
                    | ((unsigned long long)(pkt >> 16) << 32);
            }
            sh[tid] = val; __syncthreads();
            for (int off = 1; off < 1024; off <<= 1) {
                unsigned long long u = (tid >= off) ? sh[tid-off] : 0ull;
                __syncthreads(); sh[tid] += u; __syncthreads();
            }
            unsigned long long exc = run + (tid ? sh[tid-1] : 0ull);
            if (idx < nbT) g_tBlk64[idx] = exc;
            run += sh[1023];
            __syncthreads();
        }
        if (tid == 0) g_n1 = (int)(run & 0xffffffffull);
    }
}

// ---------------- rank lookup via group masks ----------------
__device__ __forceinline__ int edge_rank(int va, int tc /*1..7*/)
{
    int g = va >> 5, q = va & 31;
    uint4 Aa = g_egrp[2*g], Bb = g_egrp[2*g+1];
    unsigned mm[7] = {Aa.x, Aa.y, Aa.z, Aa.w, Bb.x, Bb.y, Bb.z};
    unsigned low = (1u << q) - 1u;
    int rk = (int)Bb.w;
#pragma unroll
    for (int x = 0; x < 7; ++x) rk += __popc(mm[x] & low);
    int tm = tc - 1;
#pragma unroll
    for (int x = 0; x < 6; ++x) if (x < tm) rk += (mm[x] >> q) & 1u;
    return rk;
}

// ---------------- kernel 5: emit interpolated vertex features ----------------
__global__ void k_verts(const float* __restrict__ feats, float* __restrict__ out,
                        int E, int S)
{
    int e = blockIdx.x*blockDim.x + threadIdx.x;
    if (e >= E) return;
    int v = e / 7;
    int tt = e - 7*v + 1;
    int g = v >> 5, q = v & 31;
    uint4 Aa = g_egrp[2*g], Bb = g_egrp[2*g+1];
    unsigned mm[7] = {Aa.x, Aa.y, Aa.z, Aa.w, Bb.x, Bb.y, Bb.z};
    int tm = tt - 1;
    if (!((mm[tm] >> q) & 1u)) return;

    unsigned low = (1u << q) - 1u;
    int rank = (int)Bb.w;
#pragma unroll
    for (int x = 0; x < 7; ++x) rank += __popc(mm[x] & low);
#pragma unroll
    for (int x = 0; x < 6; ++x) if (x < tm) rank += (mm[x] >> q) & 1u;

    int S2 = S*S;
    int v2 = v + ((tt>>2)&1)*S2 + ((tt>>1)&1)*S + (tt&1);
    float sa = g_sdf[v], sb = g_sdf[v2];
    float inv = 1.0f / (sa - sb);
    float wa = -sb * inv, wb = sa * inv;
    float* o = out + (size_t)rank * 6;
    o[0] = wa*g_rot[3*v+0] + wb*g_rot[3*v2+0];
    o[1] = wa*g_rot[3*v+1] + wb*g_rot[3*v2+1];
    o[2] = wa*g_rot[3*v+2] + wb*g_rot[3*v2+2];
    const float* fa = feats + (size_t)v  * 6 + 3;
    const float* fb = feats + (size_t)v2 * 6 + 3;
    o[3] = wa*fa[0] + wb*fb[0];
    o[4] = wa*fa[1] + wb*fb[1];
    o[5] = wa*fa[2] + wb*fb[2];
}

// ---------------- kernel 6: emit faces ----------------
__global__ void k_faces(float* __restrict__ out, int T, int R, int S)
{
    int r = blockIdx.x*blockDim.x + threadIdx.x;
    if (r >= T) return;
    int R3 = R*R*R;
    int p = r / R3, c = r - p*R3;
    unsigned code = g_cubeCode[c];
    int P0 = c_path[p][0], P1 = c_path[p][1], P2 = c_path[p][2], P3 = c_path[p][3];
    int ti = ((code >> P0) & 1) | (((code >> P1) & 1) << 1)
           | (((code >> P2) & 1) << 2) | (((code >> P3) & 1) << 3);
    int nt = c_ntri[ti];
    if (!nt) return;

    int R2 = R*R, S2 = S*S;
    int i = c / R2; int rem = c - i*R2; int j = rem / R; int k = rem - j*R;
    int v000 = (i*S + j)*S + k;
    int P[4] = {P0, P1, P2, P3};
    const int ea[6] = {0,0,0,1,1,2};
    const int eb[6] = {1,2,3,2,3,3};
    int er[6];
#pragma unroll
    for (int s = 0; s < 6; ++s) {
        int na = P[ea[s]], nb = P[eb[s]];
        int va = v000 + ((na>>2)&1)*S2 + ((na>>1)&1)*S + (na&1);
        er[s] = edge_rank(va, na ^ nb);
    }

    unsigned sc = g_tetScan[r];
    unsigned long long bk = g_tBlk64[r >> 11];
    int s1 = (int)(sc & 0xffffu) + (int)(unsigned)(bk & 0xffffffffull);
    int s2 = (int)(sc >> 16)     + (int)(unsigned)(bk >> 32);
    size_t vbase = (size_t)g_nv * 6;
    const int* tt = c_tri[ti];

    if (nt == 1) {
        size_t o = vbase + (size_t)s1 * 3;
        out[o+0] = (float)er[tt[0]];
        out[o+1] = (float)er[tt[1]];
        out[o+2] = (float)er[tt[2]];
    } else {
        size_t o = vbase + ((size_t)g_n1 + 2*(size_t)s2) * 3;
#pragma unroll
        for (int q = 0; q < 6; ++q)
            out[o+q] = (float)er[tt[q]];
    }
}

// ---------------- launch ----------------
extern "C" void kernel_launch(void* const* d_in, const int* in_sizes, int n_in,
                              void* d_out, int out_size)
{
    const float* feats  = (const float*)d_in[0];
    const float* sdf_n  = (const float*)d_in[1];
    const float* dir    = (const float*)d_in[2];
    const float* rotm   = (const float*)d_in[3];
    const float* scales = (const float*)d_in[4];

    int N = in_sizes[1];
    int S = 1;
    while ((long long)S*S*S < (long long)N) ++S;   // S = R+1
    int R = S - 1;
    int E = 7*N;
    int T = 6*R*R*R;
    int NC = R*R*R;
    int NG = (N + 31) >> 5;
    float dscale = 4.0f / (float)R;
    float* out = (float*)d_out;

    int nbT = (T + SCAN_CHUNK - 1) / SCAN_CHUNK;
    int ngrp = (NC > NG) ? NC : NG;

    k_prep <<<(N + 255)/256, 256>>>(sdf_n, dir, rotm, scales, N, dscale);
    k_grp  <<<(ngrp + 255)/256, 256>>>(N, S, NG, NC, R);
    k_tscan<<<nbT, SCAN_B>>>(T, R);
    k_mid  <<<2, 1024>>>(NG, nbT);
    k_verts<<<(E + 255)/256, 256>>>(feats, out, E, S);
    k_faces<<<(T + 255)/256, 256>>>(out, T, R, S);
}

// round 5
// speedup vs baseline: 1.1715x; 1.1478x over previous
#include <cuda_runtime.h>
#include <math.h>

// ---------------- static scratch ----------------
#define SMAX   65
#define NMAXV  (SMAX*SMAX*SMAX)       // 274625 vertices
#define NWPAD  8832                   // occ bit-words + pad for max offset reads
#define NGMAX  9216                   // 32-anchor edge groups (padded)
#define NCMAX  (64*64*64)             // cubes
#define TMAX   (6*NCMAX)              // tets
#define SCAN_B 256
#define SCAN_I 8
#define SCAN_CHUNK 2048
#define MAXBLK 1024
#define MID_IT 9                      // ceil(NGMAX/1024)

__device__ unsigned           g_occw[NWPAD];      // bit-packed occupancy (pad stays 0)
__device__ float              g_sdf[NMAXV];       // tanh(sdf)
__device__ float              g_rot[3*NMAXV];     // scale * R^T @ [d0,d1,1]
__device__ uint4              g_egrp[NGMAX*2];    // per group: 7 masks + exclusive base
__device__ int                g_eGrpCnt[NGMAX];
__device__ unsigned char      g_cubeCode[NCMAX];  // 8-bit corner occupancy per cube
__device__ unsigned           g_tetScan[TMAX];    // packed (cnt1 lo16 | cnt2 hi16) local scan
__device__ unsigned           g_tBlkP[MAXBLK];    // packed per-block sums
__device__ unsigned long long g_tBlk64[MAXBLK];   // widened exclusive block offsets
__device__ int                g_nv;               // total crossing edges (= output verts)
__device__ int                g_n1;               // total 1-triangle tets

__constant__ int c_path[6][4] = {
    {0,4,6,7},{0,4,5,7},{0,2,6,7},{0,2,3,7},{0,1,5,7},{0,1,3,7}};
__constant__ int c_ntri[16] = {0,1,1,2,1,2,2,1,1,2,2,1,2,1,1,0};
__constant__ int c_tri[16][6] = {
    {-1,-1,-1,-1,-1,-1},
    { 1, 0, 2,-1,-1,-1},
    { 4, 0, 3,-1,-1,-1},
    { 1, 4, 2, 1, 3, 4},
    { 3, 1, 5,-1,-1,-1},
    { 2, 3, 0, 2, 5, 3},
    { 1, 4, 0, 1, 5, 4},
    { 4, 2, 5,-1,-1,-1},
    { 4, 5, 2,-1,-1,-1},
    { 4, 1, 0, 4, 5, 1},
    { 3, 2, 0, 3, 5, 2},
    { 1, 3, 5,-1,-1,-1},
    { 4, 1, 2, 4, 3, 1},
    { 3, 0, 4,-1,-1,-1},
    { 2, 0, 1,-1,-1,-1},
    {-1,-1,-1,-1,-1,-1}};

__device__ __forceinline__ unsigned bits32(int b)
{
    unsigned w0 = g_occw[b >> 5];
    unsigned w1 = g_occw[(b >> 5) + 1];
    return __funnelshift_r(w0, w1, b & 31);
}

// shuffle-based exclusive block scan (u32); returns exclusive prefix; *tot = block total
// NOTE: warp-0 reduction runs shuffles with ALL 32 lanes active (UB/hang otherwise).
template<int NT>
__device__ __forceinline__ unsigned blk_exscan_u32(unsigned v, int tid, unsigned* tot)
{
    constexpr int NW = NT/32;
    __shared__ unsigned ws[NW];
    int lane = tid & 31, w = tid >> 5;
    unsigned x = v;
#pragma unroll
    for (int o = 1; o < 32; o <<= 1) {
        unsigned y = __shfl_up_sync(0xffffffffu, x, o);
        if (lane >= o) x += y;
    }
    if (lane == 31) ws[w] = x;
    __syncthreads();
    if (w == 0) {
        unsigned t = (lane < NW) ? ws[lane] : 0u;
#pragma unroll
        for (int o = 1; o < NW; o <<= 1) {
            unsigned y = __shfl_up_sync(0xffffffffu, t, o);
            if (lane >= o) t += y;
        }
        if (lane < NW) ws[lane] = t;
    }
    __syncthreads();
    unsigned base = w ? ws[w-1] : 0u;
    *tot = ws[NW - 1];
    return base + x - v;
}

template<int NT>
__device__ __forceinline__ unsigned long long blk_exscan_u64(unsigned long long v, int tid,
                                                             unsigned long long* tot)
{
    constexpr int NW = NT/32;
    __shared__ unsigned long long ws[NW];
    int lane = tid & 31, w = tid >> 5;
    unsigned long long x = v;
#pragma unroll
    for (int o = 1; o < 32; o <<= 1) {
        unsigned long long y = __shfl_up_sync(0xffffffffu, x, o);
        if (lane >= o) x += y;
    }
    if (lane == 31) ws[w] = x;
    __syncthreads();
    if (w == 0) {
        unsigned long long t = (lane < NW) ? ws[lane] : 0ull;
#pragma unroll
        for (int o = 1; o < NW; o <<= 1) {
            unsigned long long y = __shfl_up_sync(0xffffffffu, t, o);
            if (lane >= o) t += y;
        }
        if (lane < NW) ws[lane] = t;
    }
    __syncthreads();
    unsigned long long base = w ? ws[w-1] : 0ull;
    *tot = ws[NW - 1];
    return base + x - v;
}

// ---------------- kernel 1: per-vertex prep + occ bit-pack ----------------
__global__ void k_prep(const float* __restrict__ sdf_n,
                       const float* __restrict__ dir,
                       const float* __restrict__ rotm,
                       const float* __restrict__ scales,
                       int N, float dscale)
{
    int v = blockIdx.x*blockDim.x + threadIdx.x;
    bool inb = v < N;
    float s = inb ? sdf_n[v] : -1.0f;
    unsigned bal = __ballot_sync(0xffffffffu, s > 0.0f);
    if ((threadIdx.x & 31) == 0) g_occw[v >> 5] = bal;
    if (!inb) return;

    g_sdf[v] = tanhf(s);
    float l0 = dscale * tanhf(dir[2*v+0]);
    float l1 = dscale * tanhf(dir[2*v+1]);
    const float* m = rotm + 9*(size_t)v;
    float sc = scales[v];
    // rotation matrix: inv(R) = R^T
    g_rot[3*v+0] = (m[0]*l0 + m[3]*l1 + m[6]) * sc;
    g_rot[3*v+1] = (m[1]*l0 + m[4]*l1 + m[7]) * sc;
    g_rot[3*v+2] = (m[2]*l0 + m[5]*l1 + m[8]) * sc;
}

// ---------------- kernel 2: edge-group masks + counts, cube codes ----------------
__global__ void k_grp(int N, int S, int NG, int NC, int R)
{
    int t = blockIdx.x*blockDim.x + threadIdx.x;
    int S2 = S*S;

    if (t < NG) {
        int v0 = t << 5;
        int i0 = v0 / S2; int rem = v0 - i0*S2; int j0 = rem / S; int k0 = rem - j0*S;
        int qw = S - k0;                               // wrap position (>=1)
        unsigned pre = (qw >= 32) ? 0xffffffffu : ((1u << (qw & 31)) - 1u);
        int j1 = j0 + 1, i1 = i0; if (j1 == S) { j1 = 0; ++i1; }
        int nvld = N - v0;
        unsigned tailm = (nvld >= 32) ? 0xffffffffu : ((1u << (nvld & 31)) - 1u);
        unsigned A = bits32(v0);
        unsigned mm[7]; int cnt = 0;
#pragma unroll
        for (int tt = 1; tt <= 7; ++tt) {
            int di = (tt>>2)&1, dj = (tt>>1)&1, dk = tt&1;
            int d = di*S2 + dj*S + dk;
            unsigned X = A ^ bits32(v0 + d);
            unsigned vm = (((i0+di < S) && (j0+dj < S)) ? pre : 0u)
                        | (((i1+di < S) && (j1+dj < S)) ? ~pre : 0u);
            if (dk && (qw - 1) < 32) vm &= ~(1u << (qw - 1));   // k == S-1 invalid
            vm &= tailm;
            mm[tt-1] = X & vm;
            cnt += __popc(mm[tt-1]);
        }
        g_egrp[2*t]   = make_uint4(mm[0], mm[1], mm[2], mm[3]);
        g_egrp[2*t+1] = make_uint4(mm[4], mm[5], mm[6], 0u);
        g_eGrpCnt[t]  = cnt;
    }

    if (t < NC) {
        int R2 = R*R;
        int i = t / R2; int rem = t - i*R2; int j = rem / R; int k = rem - j*R;
        int b = (i*S + j)*S + k;
        unsigned p00 = bits32(b)          & 3u;
        unsigned p01 = bits32(b + S)      & 3u;
        unsigned p10 = bits32(b + S2)     & 3u;
        unsigned p11 = bits32(b + S2 + S) & 3u;
        g_cubeCode[t] = (unsigned char)(p00 | (p01 << 2) | (p10 << 4) | (p11 << 6));
    }
}

// ---------------- kernel 3: tet classify + packed scan ----------------
__global__ void k_tscan(int T, int R)
{
    int tid = threadIdx.x;
    int base = blockIdx.x*SCAN_CHUNK + tid*SCAN_I;
    int R3 = R*R*R;
    unsigned loc[SCAN_I], sum = 0u;
#pragma unroll
    for (int it = 0; it < SCAN_I; ++it) {
        int r = base + it;
        unsigned add = 0u;
        if (r < T) {
            int p = r / R3, c = r - p*R3;
            unsigned code = g_cubeCode[c];
            int ti = ((code >> c_path[p][0]) & 1)
                   | (((code >> c_path[p][1]) & 1) << 1)
                   | (((code >> c_path[p][2]) & 1) << 2)
                   | (((code >> c_path[p][3]) & 1) << 3);
            int nt = c_ntri[ti];
            add = (nt == 1) ? 1u : ((nt == 2) ? 0x10000u : 0u);
        }
        loc[it] = sum; sum += add;
    }
    unsigned tot;
    unsigned exc = blk_exscan_u32<SCAN_B>(sum, tid, &tot);
#pragma unroll
    for (int it = 0; it < SCAN_I; ++it) {
        int r = base + it;
        if (r < T) g_tetScan[r] = exc + loc[it];
    }
    if (tid == SCAN_B-1) g_tBlkP[blockIdx.x] = tot;
}

// ---------------- kernel 4: both mid-level scans (2 blocks, single pass) ----------------
__global__ void k_mid(int NG, int nbT)
{
    int tid = threadIdx.x;
    if (blockIdx.x == 0) {
        // edge-group exclusive scan: MID_IT consecutive groups per thread
        int base = tid * MID_IT;
        int loc[MID_IT]; int sum = 0;
#pragma unroll
        for (int it = 0; it < MID_IT; ++it) {
            int idx = base + it;
            int v = (idx < NG) ? g_eGrpCnt[idx] : 0;
            loc[it] = sum; sum += v;
        }
        unsigned tot;
        unsigned exc = blk_exscan_u32<1024>((unsigned)sum, tid, &tot);
#pragma unroll
        for (int it = 0; it < MID_IT; ++it) {
            int idx = base + it;
            if (idx < NG) ((unsigned*)g_egrp)[idx*8 + 7] = exc + (unsigned)loc[it];
        }
        if (tid == 0) g_nv = (int)tot;
    } else {
        // tet block-sum exclusive scan (nbT <= 1024): widen packed 16|16 -> 32|32
        unsigned long long v = 0ull;
        if (tid < nbT) {
            unsigned pkt = g_tBlkP[tid];
            v = (unsigned long long)(pkt & 0xffffu)
              | ((unsigned long long)(pkt >> 16) << 32);
        }
        unsigned long long tot;
        unsigned long long exc = blk_exscan_u64<1024>(v, tid, &tot);
        if (tid < nbT) g_tBlk64[tid] = exc;
        if (tid == 0) g_n1 = (int)(tot & 0xffffffffull);
    }
}

// ---------------- rank lookup via group masks ----------------
__device__ __forceinline__ int edge_rank(int va, int tc /*1..7*/)
{
    int g = va >> 5, q = va & 31;
    uint4 Aa = g_egrp[2*g], Bb = g_egrp[2*g+1];
    unsigned mm[7] = {Aa.x, Aa.y, Aa.z, Aa.w, Bb.x, Bb.y, Bb.z};
    unsigned low = (1u << q) - 1u;
    int rk = (int)Bb.w;
#pragma unroll
    for (int x = 0; x < 7; ++x) rk += __popc(mm[x] & low);
    int tm = tc - 1;
#pragma unroll
    for (int x = 0; x < 6; ++x) if (x < tm) rk += (mm[x] >> q) & 1u;
    return rk;
}

// ---------------- kernel 5: emit interpolated vertex features ----------------
__global__ void k_verts(const float* __restrict__ feats, float* __restrict__ out,
                        int E, int S)
{
    int e = blockIdx.x*blockDim.x + threadIdx.x;
    if (e >= E) return;
    int v = e / 7;
    int tt = e - 7*v + 1;
    int g = v >> 5, q = v & 31;
    uint4 Aa = g_egrp[2*g], Bb = g_egrp[2*g+1];
    unsigned mm[7] = {Aa.x, Aa.y, Aa.z, Aa.w, Bb.x, Bb.y, Bb.z};
    int tm = tt - 1;
    if (!((mm[tm] >> q) & 1u)) return;

    unsigned low = (1u << q) - 1u;
    int rank = (int)Bb.w;
#pragma unroll
    for (int x = 0; x < 7; ++x) rank += __popc(mm[x] & low);
#pragma unroll
    for (int x = 0; x < 6; ++x) if (x < tm) rank += (mm[x] >> q) & 1u;

    int S2 = S*S;
    int v2 = v + ((tt>>2)&1)*S2 + ((tt>>1)&1)*S + (tt&1);
    float sa = g_sdf[v], sb = g_sdf[v2];
    float inv = 1.0f / (sa - sb);
    float wa = -sb * inv, wb = sa * inv;
    float* o = out + (size_t)rank * 6;
    o[0] = wa*g_rot[3*v+0] + wb*g_rot[3*v2+0];
    o[1] = wa*g_rot[3*v+1] + wb*g_rot[3*v2+1];
    o[2] = wa*g_rot[3*v+2] + wb*g_rot[3*v2+2];
    const float* fa = feats + (size_t)v  * 6 + 3;
    const float* fb = feats + (size_t)v2 * 6 + 3;
    o[3] = wa*fa[0] + wb*fb[0];
    o[4] = wa*fa[1] + wb*fb[1];
    o[5] = wa*fa[2] + wb*fb[2];
}

// ---------------- kernel 6: emit faces ----------------
__global__ void k_faces(float* __restrict__ out, int T, int R, int S)
{
    int r = blockIdx.x*blockDim.x + threadIdx.x;
    if (r >= T) return;
    int R3 = R*R*R;
    int p = r / R3, c = r - p*R3;
    unsigned code = g_cubeCode[c];
    int P0 = c_path[p][0], P1 = c_path[p][1], P2 = c_path[p][2], P3 = c_path[p][3];
    int ti = ((code >> P0) & 1) | (((code >> P1) & 1) << 1)
           | (((code >> P2) & 1) << 2) | (((code >> P3) & 1) << 3);
    int nt = c_ntri[ti];
    if (!nt) return;

    int R2 = R*R, S2 = S*S;
    int i = c / R2; int rem = c - i*R2; int j = rem / R; int k = rem - j*R;
    int v000 = (i*S + j)*S + k;
    int P[4] = {P0, P1, P2, P3};
    const int ea[6] = {0,0,0,1,1,2};
    const int eb[6] = {1,2,3,2,3,3};
    int er[6];
#pragma unroll
    for (int s = 0; s < 6; ++s) {
        int na = P[ea[s]], nb = P[eb[s]];
        int va = v000 + ((na>>2)&1)*S2 + ((na>>1)&1)*S + (na&1);
        er[s] = edge_rank(va, na ^ nb);
    }

    unsigned sc = g_tetScan[r];
    unsigned long long bk = g_tBlk64[r >> 11];
    int s1 = (int)(sc & 0xffffu) + (int)(unsigned)(bk & 0xffffffffull);
    int s2 = (int)(sc >> 16)     + (int)(unsigned)(bk >> 32);
    size_t vbase = (size_t)g_nv * 6;
    const int* tt = c_tri[ti];

    if (nt == 1) {
        size_t o = vbase + (size_t)s1 * 3;
        out[o+0] = (float)er[tt[0]];
        out[o+1] = (float)er[tt[1]];
        out[o+2] = (float)er[tt[2]];
    } else {
        size_t o = vbase + ((size_t)g_n1 + 2*(size_t)s2) * 3;
#pragma unroll
        for (int q = 0; q < 6; ++q)
            out[o+q] = (float)er[tt[q]];
    }
}

// ---------------- launch ----------------
extern "C" void kernel_launch(void* const* d_in, const int* in_sizes, int n_in,
                              void* d_out, int out_size)
{
    const float* feats  = (const float*)d_in[0];
    const float* sdf_n  = (const float*)d_in[1];
    const float* dir    = (const float*)d_in[2];
    const float* rotm   = (const float*)d_in[3];
    const float* scales = (const float*)d_in[4];

    int N = in_sizes[1];
    int S = 1;
    while ((long long)S*S*S < (long long)N) ++S;   // S = R+1
    int R = S - 1;
    int E = 7*N;
    int T = 6*R*R*R;
    int NC = R*R*R;
    int NG = (N + 31) >> 5;
    float dscale = 4.0f / (float)R;
    float* out = (float*)d_out;

    int nbT = (T + SCAN_CHUNK - 1) / SCAN_CHUNK;
    int ngrp = (NC > NG) ? NC : NG;

    k_prep <<<(N + 255)/256, 256>>>(sdf_n, dir, rotm, scales, N, dscale);
    k_grp  <<<(ngrp + 255)/256, 256>>>(N, S, NG, NC, R);
    k_tscan<<<nbT, SCAN_B>>>(T, R);
    k_mid  <<<2, 1024>>>(NG, nbT);
    k_verts<<<(E + 127)/128, 128>>>(feats, out, E, S);
    k_faces<<<(T + 127)/128, 128>>>(out, T, R, S);
}